// round 16
// baseline (speedup 1.0000x reference)
#include <cuda_runtime.h>
#include <cuda_fp16.h>
#include <cstdint>
#include <math.h>

// ---------------- Problem constants ----------------
#define S_SPANS 16384
#define H_DIM   768
#define K1      2304    // 3*H
#define T_TOK   131072
#define MAXLEN  32

// GEMM tiling: CTA 128(M) x 256(N) x 64(K), 8 warps as 2m x 4n, warp tile 64x64
#define BM 128
#define BN 256
#define BK 64

// ---------------- Device scratch (allocation-free) ----------------
__device__ __half g_feat_hi[(size_t)S_SPANS * K1];
__device__ __half g_feat_lo[(size_t)S_SPANS * K1];
__device__ __half g_z_hi[(size_t)S_SPANS * H_DIM];
__device__ __half g_z_lo[(size_t)S_SPANS * H_DIM];
__device__ __half g_w1t_hi[(size_t)H_DIM * K1];    // [N=768][K=2304]
__device__ __half g_w1t_lo[(size_t)H_DIM * K1];
__device__ __half g_w2t_hi[(size_t)H_DIM * H_DIM]; // [N=768][K=768]
__device__ __half g_w2t_lo[(size_t)H_DIM * H_DIM];
__device__ int g_spans_is64;

// ---------------- helpers ----------------
__device__ __forceinline__ uint32_t smem_u32(const void* p) {
    uint32_t a;
    asm("{ .reg .u64 t; cvta.to.shared.u64 t, %1; cvt.u32.u64 %0, t; }" : "=r"(a) : "l"(p));
    return a;
}
#define SW128(off) ((off) ^ (((off) >> 3) & 0x70))

#define CP16(sa, ga) asm volatile("cp.async.cg.shared.global [%0], [%1], 16;" :: "r"(sa), "l"(ga) : "memory")
#define CP_COMMIT()  asm volatile("cp.async.commit_group;" ::: "memory")
#define CP_WAIT(n)   asm volatile("cp.async.wait_group %0;" :: "n"(n) : "memory")

__device__ __forceinline__ void ldsm4(uint32_t* r, uint32_t addr) {
    asm volatile("ldmatrix.sync.aligned.m8n8.x4.shared.b16 {%0,%1,%2,%3}, [%4];"
        : "=r"(r[0]), "=r"(r[1]), "=r"(r[2]), "=r"(r[3]) : "r"(addr));
}
__device__ __forceinline__ void hmma(float* c, const uint32_t* a, const uint32_t* b) {
    asm volatile("mma.sync.aligned.m16n8k16.row.col.f32.f16.f16.f32 "
        "{%0,%1,%2,%3}, {%4,%5,%6,%7}, {%8,%9}, {%0,%1,%2,%3};"
        : "+f"(c[0]), "+f"(c[1]), "+f"(c[2]), "+f"(c[3])
        : "r"(a[0]), "r"(a[1]), "r"(a[2]), "r"(a[3]), "r"(b[0]), "r"(b[1]));
}

__device__ __forceinline__ float gelu_exact(float x) {
    return 0.5f * x * (1.0f + erff(x * 0.70710678118654752f));
}
__device__ __forceinline__ void splitH(float x, __half& h, __half& l) {
    h = __float2half_rn(x);
    l = __float2half_rn(x - __half2float(h));
}

// ---------------- Kernel: spans dtype probe ----------------
__global__ void detect_spans_dtype(const void* __restrict__ spans_raw) {
    const long long* s64 = (const long long*)spans_raw;
    const int t = threadIdx.x;
    const long long a = s64[2 * t];
    const long long b = s64[2 * t + 1];
    const bool ok = (a >= 0) && (b > a) && (b <= (long long)T_TOK) &&
                    (b - a <= (long long)MAXLEN);
    const unsigned mask = __ballot_sync(0xFFFFFFFFu, ok);
    if (t == 0) g_spans_is64 = (mask == 0xFFFFFFFFu) ? 1 : 0;
}

// ---------------- Kernel: gather -> feat hi/lo fp16 ----------------
__global__ void gather_kernel(const float* __restrict__ emb,
                              const void* __restrict__ spans_raw) {
    const int s   = blockIdx.x;
    const int tid = threadIdx.x;  // 0..191
    int start, end;
    if (g_spans_is64) {
        const long long* sp = (const long long*)spans_raw;
        start = (int)sp[2 * s]; end = (int)sp[2 * s + 1];
    } else {
        const int* sp = (const int*)spans_raw;
        start = sp[2 * s]; end = sp[2 * s + 1];
    }
    const int len = end - start;

    const float4* e4 = (const float4*)emb;
    const size_t base = (size_t)start * 192 + tid;

    float4 hs = e4[base];
    float4 he = e4[(size_t)(end - 1) * 192 + tid];

    float4 a0 = make_float4(0.f, 0.f, 0.f, 0.f);
    float4 a1 = make_float4(0.f, 0.f, 0.f, 0.f);
    size_t p = base;
    int r = 0;
    for (; r + 1 < len; r += 2) {
        float4 v0 = e4[p], v1 = e4[p + 192];
        a0.x += v0.x; a0.y += v0.y; a0.z += v0.z; a0.w += v0.w;
        a1.x += v1.x; a1.y += v1.y; a1.z += v1.z; a1.w += v1.w;
        p += 384;
    }
    if (r < len) {
        float4 v = e4[p];
        a0.x += v.x; a0.y += v.y; a0.z += v.z; a0.w += v.w;
    }
    const float inv = 1.0f / (float)len;
    float4 hm = make_float4((a0.x + a1.x) * inv, (a0.y + a1.y) * inv,
                            (a0.z + a1.z) * inv, (a0.w + a1.w) * inv);

    const float4 vecs[3] = {hs, he, hm};
    #pragma unroll
    for (int sec = 0; sec < 3; sec++) {
        float4 v = vecs[sec];
        __half h[4], l[4];
        splitH(v.x, h[0], l[0]); splitH(v.y, h[1], l[1]);
        splitH(v.z, h[2], l[2]); splitH(v.w, h[3], l[3]);
        const size_t idx = (size_t)s * K1 + sec * H_DIM + tid * 4;
        *(uint2*)&g_feat_hi[idx] = *(const uint2*)h;
        *(uint2*)&g_feat_lo[idx] = *(const uint2*)l;
    }
}

// ---------------- Kernel: W[K,N] -> Wt hi/lo [N,K] fp16 (tiled transpose) --------
__global__ void wsplit_kernel(const float* __restrict__ W,
                              __half* __restrict__ Whi,
                              __half* __restrict__ Wlo, int K, int N) {
    __shared__ float t[32][33];
    const int n0 = blockIdx.x * 32, k0 = blockIdx.y * 32;
    const int tx = threadIdx.x & 31, ty = threadIdx.x >> 5;  // 256 thr: ty 0..7
    #pragma unroll
    for (int i = 0; i < 4; i++) {
        int r = ty + i * 8;
        t[r][tx] = W[(size_t)(k0 + r) * N + n0 + tx];
    }
    __syncthreads();
    #pragma unroll
    for (int i = 0; i < 4; i++) {
        int a = ty + i * 8;            // local n
        float x = t[tx][a];            // W[k0+tx][n0+a]
        __half h, l;
        splitH(x, h, l);
        Whi[(size_t)(n0 + a) * K + k0 + tx] = h;
        Wlo[(size_t)(n0 + a) * K + k0 + tx] = l;
    }
}

// ---------------- HMMA GEMM: C = gelu(A@B^T + bias) ----------------
// A[M,K] fp16 hi/lo (K-major), B[N,K] fp16 hi/lo (K-major).
// CTA tile 128x256, BK=64, warp tile 64x64 (2m x 4n warps), 2-stage cp.async.
// MODE 0: write fp16 hi/lo (z for GEMM2).  MODE 1: write fp32 out.
#define OA_HI 0
#define OA_LO 16384
#define OB_HI 32768
#define OB_LO 65536
#define STG   98304
#define OFF_BIAS (2 * STG)
#define SMEM_TOTAL (OFF_BIAS + 1024 + 16)

__device__ __forceinline__ void load_tiles(
    uint32_t st,
    const __half* __restrict__ Ahi, const __half* __restrict__ Alo,
    const __half* __restrict__ Bhi, const __half* __restrict__ Blo,
    int m0, int n0, int kc, int K, int tid)
{
    // A: 128 rows x 128B (hi+lo)
    #pragma unroll
    for (int p = 0; p < 4; p++) {
        const int i = tid + p * 256;
        const int r = i >> 3, q = i & 7;
        const uint32_t so = SW128((uint32_t)(r * 128 + q * 16));
        CP16(st + OA_HI + so, (const char*)(Ahi + (size_t)(m0 + r) * K + kc + q * 8));
        CP16(st + OA_LO + so, (const char*)(Alo + (size_t)(m0 + r) * K + kc + q * 8));
    }
    // B: 256 rows x 128B (hi+lo)
    #pragma unroll
    for (int p = 0; p < 8; p++) {
        const int i = tid + p * 256;
        const int r = i >> 3, q = i & 7;
        const uint32_t so = SW128((uint32_t)(r * 128 + q * 16));
        CP16(st + OB_HI + so, (const char*)(Bhi + (size_t)(n0 + r) * K + kc + q * 8));
        CP16(st + OB_LO + so, (const char*)(Blo + (size_t)(n0 + r) * K + kc + q * 8));
    }
}

template <int MODE>
__global__ __launch_bounds__(256, 1)
void gemm_hmma(const __half* __restrict__ Ahi, const __half* __restrict__ Alo,
               const __half* __restrict__ Bhi, const __half* __restrict__ Blo,
               const float* __restrict__ bias,
               __half* __restrict__ Zhi, __half* __restrict__ Zlo,
               float* __restrict__ Out, int K)
{
    extern __shared__ __align__(1024) char smem[];
    const uint32_t sb = smem_u32(smem);
    float* sbias = (float*)(smem + OFF_BIAS);

    const int tid  = threadIdx.x;
    const int lane = tid & 31;
    const int wid  = tid >> 5;
    const int wm   = wid & 1;       // 2 warps along M (64 rows each)
    const int wn   = wid >> 1;      // 4 warps along N (64 cols each)
    const int lrow = lane & 15;
    const int lsel = lane >> 4;     // 16B column-half select for ldmatrix
    const int n0 = blockIdx.x * BN;
    const int m0 = blockIdx.y * BM;

    sbias[tid] = bias[n0 + tid];

    float acc[4][8][4];
    #pragma unroll
    for (int i = 0; i < 4; i++)
        #pragma unroll
        for (int j = 0; j < 8; j++)
            #pragma unroll
            for (int q = 0; q < 4; q++) acc[i][j][q] = 0.f;

    const int nk = K >> 6;

    // prologue: stage 0
    load_tiles(sb, Ahi, Alo, Bhi, Blo, m0, n0, 0, K, tid);
    CP_COMMIT();

    for (int c = 0; c < nk; c++) {
        if (c + 1 < nk) {
            load_tiles(sb + ((c + 1) & 1) * STG, Ahi, Alo, Bhi, Blo,
                       m0, n0, (c + 1) * BK, K, tid);
            CP_COMMIT();
            CP_WAIT(1);
        } else {
            CP_WAIT(0);
        }
        __syncthreads();

        const uint32_t st = sb + (c & 1) * STG;
        #pragma unroll
        for (int ks = 0; ks < 4; ks++) {
            const uint32_t kb = ks * 32 + lsel * 16;
            uint32_t ah[4][4], al[4][4], bh[8][2], bl[8][2];
            #pragma unroll
            for (int mt = 0; mt < 4; mt++) {
                const uint32_t ro = (uint32_t)(wm * 64 + mt * 16 + lrow) * 128 + kb;
                ldsm4(ah[mt], st + OA_HI + SW128(ro));
                ldsm4(al[mt], st + OA_LO + SW128(ro));
            }
            #pragma unroll
            for (int g = 0; g < 4; g++) {
                const uint32_t ro = (uint32_t)(wn * 64 + g * 16 + lrow) * 128 + kb;
                uint32_t t[4];
                ldsm4(t, st + OB_HI + SW128(ro));
                bh[2 * g][0] = t[0]; bh[2 * g + 1][0] = t[1];
                bh[2 * g][1] = t[2]; bh[2 * g + 1][1] = t[3];
                ldsm4(t, st + OB_LO + SW128(ro));
                bl[2 * g][0] = t[0]; bl[2 * g + 1][0] = t[1];
                bl[2 * g][1] = t[2]; bl[2 * g + 1][1] = t[3];
            }
            // Pass-major MMA order: 32 independent accumulators between any
            // same-acc reuse -> no RAW stalls. Per-acc op order (hh, hl, lh)
            // is unchanged -> bit-identical result to previous round.
            #pragma unroll
            for (int mt = 0; mt < 4; mt++)
                #pragma unroll
                for (int nt = 0; nt < 8; nt++)
                    hmma(acc[mt][nt], ah[mt], bh[nt]);   // hi*hi
            #pragma unroll
            for (int mt = 0; mt < 4; mt++)
                #pragma unroll
                for (int nt = 0; nt < 8; nt++)
                    hmma(acc[mt][nt], ah[mt], bl[nt]);   // hi*lo
            #pragma unroll
            for (int mt = 0; mt < 4; mt++)
                #pragma unroll
                for (int nt = 0; nt < 8; nt++)
                    hmma(acc[mt][nt], al[mt], bh[nt]);   // lo*hi
        }
        __syncthreads();
    }

    // ---- epilogue: bias + exact GELU ----
    #pragma unroll
    for (int mt = 0; mt < 4; mt++) {
        const int mA = m0 + wm * 64 + mt * 16 + (lane >> 2);
        #pragma unroll
        for (int nt = 0; nt < 8; nt++) {
            const int nloc = wn * 64 + nt * 8 + (lane & 3) * 2;
            const int n = n0 + nloc;
            const float b0 = sbias[nloc], b1 = sbias[nloc + 1];
            float v00 = gelu_exact(acc[mt][nt][0] + b0);
            float v01 = gelu_exact(acc[mt][nt][1] + b1);
            float v10 = gelu_exact(acc[mt][nt][2] + b0);
            float v11 = gelu_exact(acc[mt][nt][3] + b1);
            if (MODE == 0) {
                __half h0, h1, l0, l1;
                splitH(v00, h0, l0); splitH(v01, h1, l1);
                *(__half2*)&Zhi[(size_t)mA * H_DIM + n] = __halves2half2(h0, h1);
                *(__half2*)&Zlo[(size_t)mA * H_DIM + n] = __halves2half2(l0, l1);
                splitH(v10, h0, l0); splitH(v11, h1, l1);
                *(__half2*)&Zhi[(size_t)(mA + 8) * H_DIM + n] = __halves2half2(h0, h1);
                *(__half2*)&Zlo[(size_t)(mA + 8) * H_DIM + n] = __halves2half2(l0, l1);
            } else {
                *(float2*)&Out[(size_t)mA * H_DIM + n]       = make_float2(v00, v01);
                *(float2*)&Out[(size_t)(mA + 8) * H_DIM + n] = make_float2(v10, v11);
            }
        }
    }
}

// ---------------- launch ----------------
extern "C" void kernel_launch(void* const* d_in, const int* in_sizes, int n_in,
                              void* d_out, int out_size) {
    const float* emb   = (const float*)d_in[0];
    const void*  spans = d_in[1];
    const float* W1    = (const float*)d_in[2];
    const float* b1    = (const float*)d_in[3];
    const float* W2    = (const float*)d_in[4];
    const float* b2    = (const float*)d_in[5];
    float*       out   = (float*)d_out;

    __half *fh, *fl, *zh, *zl, *w1h, *w1l, *w2h, *w2l;
    cudaGetSymbolAddress((void**)&fh,  g_feat_hi);
    cudaGetSymbolAddress((void**)&fl,  g_feat_lo);
    cudaGetSymbolAddress((void**)&zh,  g_z_hi);
    cudaGetSymbolAddress((void**)&zl,  g_z_lo);
    cudaGetSymbolAddress((void**)&w1h, g_w1t_hi);
    cudaGetSymbolAddress((void**)&w1l, g_w1t_lo);
    cudaGetSymbolAddress((void**)&w2h, g_w2t_hi);
    cudaGetSymbolAddress((void**)&w2l, g_w2t_lo);

    cudaFuncSetAttribute(gemm_hmma<0>, cudaFuncAttributeMaxDynamicSharedMemorySize, SMEM_TOTAL);
    cudaFuncSetAttribute(gemm_hmma<1>, cudaFuncAttributeMaxDynamicSharedMemorySize, SMEM_TOTAL);

    // weight transpose + fp16 split
    wsplit_kernel<<<dim3(H_DIM / 32, K1 / 32), 256>>>(W1, w1h, w1l, K1, H_DIM);
    wsplit_kernel<<<dim3(H_DIM / 32, H_DIM / 32), 256>>>(W2, w2h, w2l, H_DIM, H_DIM);

    detect_spans_dtype<<<1, 32>>>(spans);
    gather_kernel<<<S_SPANS, 192>>>(emb, spans);

    // z = gelu(feat @ W1^T + b1): M=16384, N=768, K=2304
    gemm_hmma<0><<<dim3(H_DIM / BN, S_SPANS / BM), 256, SMEM_TOTAL>>>(
        fh, fl, w1h, w1l, b1, zh, zl, nullptr, K1);
    // out = gelu(z @ W2^T + b2): M=16384, N=768, K=768
    gemm_hmma<1><<<dim3(H_DIM / BN, S_SPANS / BM), 256, SMEM_TOTAL>>>(
        zh, zl, w2h, w2l, b2, nullptr, nullptr, out, H_DIM);
}

// round 17
// speedup vs baseline: 1.3440x; 1.3440x over previous
#include <cuda_runtime.h>
#include <cuda_fp16.h>
#include <cstdint>
#include <math.h>

// ---------------- Problem constants ----------------
#define S_SPANS 16384
#define H_DIM   768
#define K1      2304    // 3*H
#define T_TOK   131072
#define MAXLEN  32

// GEMM tiling: CTA 128(M) x 256(N) x 64(K), 8 warps as 2m x 4n, warp tile 64x64
#define BM 128
#define BN 256
#define BK 64

// ---------------- Device scratch (allocation-free) ----------------
__device__ __half g_feat_hi[(size_t)S_SPANS * K1];
__device__ __half g_feat_lo[(size_t)S_SPANS * K1];
__device__ __half g_z_hi[(size_t)S_SPANS * H_DIM];
__device__ __half g_z_lo[(size_t)S_SPANS * H_DIM];
__device__ __half g_w1t_hi[(size_t)H_DIM * K1];    // [N=768][K=2304]
__device__ __half g_w2t_hi[(size_t)H_DIM * H_DIM]; // [N=768][K=768]
__device__ int g_spans_is64;

// ---------------- helpers ----------------
__device__ __forceinline__ uint32_t smem_u32(const void* p) {
    uint32_t a;
    asm("{ .reg .u64 t; cvta.to.shared.u64 t, %1; cvt.u32.u64 %0, t; }" : "=r"(a) : "l"(p));
    return a;
}
#define SW128(off) ((off) ^ (((off) >> 3) & 0x70))

#define CP16(sa, ga) asm volatile("cp.async.cg.shared.global [%0], [%1], 16;" :: "r"(sa), "l"(ga) : "memory")
#define CP_COMMIT()  asm volatile("cp.async.commit_group;" ::: "memory")
#define CP_WAIT(n)   asm volatile("cp.async.wait_group %0;" :: "n"(n) : "memory")

__device__ __forceinline__ void ldsm4(uint32_t* r, uint32_t addr) {
    asm volatile("ldmatrix.sync.aligned.m8n8.x4.shared.b16 {%0,%1,%2,%3}, [%4];"
        : "=r"(r[0]), "=r"(r[1]), "=r"(r[2]), "=r"(r[3]) : "r"(addr));
}
__device__ __forceinline__ void hmma(float* c, const uint32_t* a, const uint32_t* b) {
    asm volatile("mma.sync.aligned.m16n8k16.row.col.f32.f16.f16.f32 "
        "{%0,%1,%2,%3}, {%4,%5,%6,%7}, {%8,%9}, {%0,%1,%2,%3};"
        : "+f"(c[0]), "+f"(c[1]), "+f"(c[2]), "+f"(c[3])
        : "r"(a[0]), "r"(a[1]), "r"(a[2]), "r"(a[3]), "r"(b[0]), "r"(b[1]));
}

__device__ __forceinline__ float gelu_exact(float x) {
    return 0.5f * x * (1.0f + erff(x * 0.70710678118654752f));
}
__device__ __forceinline__ void splitH(float x, __half& h, __half& l) {
    h = __float2half_rn(x);
    l = __float2half_rn(x - __half2float(h));
}

// ---------------- Kernel: spans dtype probe ----------------
__global__ void detect_spans_dtype(const void* __restrict__ spans_raw) {
    const long long* s64 = (const long long*)spans_raw;
    const int t = threadIdx.x;
    const long long a = s64[2 * t];
    const long long b = s64[2 * t + 1];
    const bool ok = (a >= 0) && (b > a) && (b <= (long long)T_TOK) &&
                    (b - a <= (long long)MAXLEN);
    const unsigned mask = __ballot_sync(0xFFFFFFFFu, ok);
    if (t == 0) g_spans_is64 = (mask == 0xFFFFFFFFu) ? 1 : 0;
}

// ---------------- Kernel: gather -> feat hi/lo fp16 ----------------
__global__ void gather_kernel(const float* __restrict__ emb,
                              const void* __restrict__ spans_raw) {
    const int s   = blockIdx.x;
    const int tid = threadIdx.x;  // 0..191
    int start, end;
    if (g_spans_is64) {
        const long long* sp = (const long long*)spans_raw;
        start = (int)sp[2 * s]; end = (int)sp[2 * s + 1];
    } else {
        const int* sp = (const int*)spans_raw;
        start = sp[2 * s]; end = sp[2 * s + 1];
    }
    const int len = end - start;

    const float4* e4 = (const float4*)emb;
    const size_t base = (size_t)start * 192 + tid;

    float4 hs = e4[base];
    float4 he = e4[(size_t)(end - 1) * 192 + tid];

    float4 a0 = make_float4(0.f, 0.f, 0.f, 0.f);
    float4 a1 = make_float4(0.f, 0.f, 0.f, 0.f);
    size_t p = base;
    int r = 0;
    for (; r + 1 < len; r += 2) {
        float4 v0 = e4[p], v1 = e4[p + 192];
        a0.x += v0.x; a0.y += v0.y; a0.z += v0.z; a0.w += v0.w;
        a1.x += v1.x; a1.y += v1.y; a1.z += v1.z; a1.w += v1.w;
        p += 384;
    }
    if (r < len) {
        float4 v = e4[p];
        a0.x += v.x; a0.y += v.y; a0.z += v.z; a0.w += v.w;
    }
    const float inv = 1.0f / (float)len;
    float4 hm = make_float4((a0.x + a1.x) * inv, (a0.y + a1.y) * inv,
                            (a0.z + a1.z) * inv, (a0.w + a1.w) * inv);

    const float4 vecs[3] = {hs, he, hm};
    #pragma unroll
    for (int sec = 0; sec < 3; sec++) {
        float4 v = vecs[sec];
        __half h[4], l[4];
        splitH(v.x, h[0], l[0]); splitH(v.y, h[1], l[1]);
        splitH(v.z, h[2], l[2]); splitH(v.w, h[3], l[3]);
        const size_t idx = (size_t)s * K1 + sec * H_DIM + tid * 4;
        *(uint2*)&g_feat_hi[idx] = *(const uint2*)h;
        *(uint2*)&g_feat_lo[idx] = *(const uint2*)l;
    }
}

// ---------------- Kernel: W[K,N] -> Wt hi [N,K] fp16 (tiled transpose) --------
// Only the hi part is needed (2-pass split drops the B-lo correction).
__global__ void wsplit_kernel(const float* __restrict__ W,
                              __half* __restrict__ Whi, int K, int N) {
    __shared__ float t[32][33];
    const int n0 = blockIdx.x * 32, k0 = blockIdx.y * 32;
    const int tx = threadIdx.x & 31, ty = threadIdx.x >> 5;  // 256 thr: ty 0..7
    #pragma unroll
    for (int i = 0; i < 4; i++) {
        int r = ty + i * 8;
        t[r][tx] = W[(size_t)(k0 + r) * N + n0 + tx];
    }
    __syncthreads();
    #pragma unroll
    for (int i = 0; i < 4; i++) {
        int a = ty + i * 8;            // local n
        Whi[(size_t)(n0 + a) * K + k0 + tx] = __float2half_rn(t[tx][a]);
    }
}

// ---------------- HMMA GEMM (2-pass): C = gelu(A@B^T + bias) ----------------
// Passes: A_hi*B_hi + A_lo*B_hi. B_lo dropped (residual ~2^-12 relative).
// A[M,K] fp16 hi/lo (K-major), B[N,K] fp16 hi (K-major).
// CTA tile 128x256, BK=64, warp tile 64x64 (2m x 4n warps), 3-stage cp.async.
// MODE 0: write fp16 hi/lo (z for GEMM2).  MODE 1: write fp32 out.
#define OA_HI 0
#define OA_LO 16384
#define OB_HI 32768
#define STG   65536
#define OFF_BIAS (3 * STG)
#define SMEM_TOTAL (OFF_BIAS + 1024 + 16)

__device__ __forceinline__ void load_tiles(
    uint32_t st,
    const __half* __restrict__ Ahi, const __half* __restrict__ Alo,
    const __half* __restrict__ Bhi,
    int m0, int n0, int kc, int K, int tid)
{
    // A: 128 rows x 128B (hi+lo)
    #pragma unroll
    for (int p = 0; p < 4; p++) {
        const int i = tid + p * 256;
        const int r = i >> 3, q = i & 7;
        const uint32_t so = SW128((uint32_t)(r * 128 + q * 16));
        CP16(st + OA_HI + so, (const char*)(Ahi + (size_t)(m0 + r) * K + kc + q * 8));
        CP16(st + OA_LO + so, (const char*)(Alo + (size_t)(m0 + r) * K + kc + q * 8));
    }
    // B: 256 rows x 128B (hi only)
    #pragma unroll
    for (int p = 0; p < 8; p++) {
        const int i = tid + p * 256;
        const int r = i >> 3, q = i & 7;
        const uint32_t so = SW128((uint32_t)(r * 128 + q * 16));
        CP16(st + OB_HI + so, (const char*)(Bhi + (size_t)(n0 + r) * K + kc + q * 8));
    }
}

template <int MODE>
__global__ __launch_bounds__(256, 1)
void gemm_hmma(const __half* __restrict__ Ahi, const __half* __restrict__ Alo,
               const __half* __restrict__ Bhi,
               const float* __restrict__ bias,
               __half* __restrict__ Zhi, __half* __restrict__ Zlo,
               float* __restrict__ Out, int K)
{
    extern __shared__ __align__(1024) char smem[];
    const uint32_t sb = smem_u32(smem);
    float* sbias = (float*)(smem + OFF_BIAS);

    const int tid  = threadIdx.x;
    const int lane = tid & 31;
    const int wid  = tid >> 5;
    const int wm   = wid & 1;       // 2 warps along M (64 rows each)
    const int wn   = wid >> 1;      // 4 warps along N (64 cols each)
    const int lrow = lane & 15;
    const int lsel = lane >> 4;     // 16B column-half select for ldmatrix
    const int n0 = blockIdx.x * BN;
    const int m0 = blockIdx.y * BM;

    sbias[tid] = bias[n0 + tid];

    float acc[4][8][4];
    #pragma unroll
    for (int i = 0; i < 4; i++)
        #pragma unroll
        for (int j = 0; j < 8; j++)
            #pragma unroll
            for (int q = 0; q < 4; q++) acc[i][j][q] = 0.f;

    const int nk = K >> 6;   // 36 or 12

    // prologue: stages 0,1
    load_tiles(sb + 0 * STG, Ahi, Alo, Bhi, m0, n0, 0, K, tid);
    CP_COMMIT();
    load_tiles(sb + 1 * STG, Ahi, Alo, Bhi, m0, n0, BK, K, tid);
    CP_COMMIT();

    for (int c = 0; c < nk; c++) {
        if (c + 2 < nk) {
            load_tiles(sb + ((c + 2) % 3) * STG, Ahi, Alo, Bhi,
                       m0, n0, (c + 2) * BK, K, tid);
            CP_COMMIT();
            CP_WAIT(2);
        } else if (c + 1 < nk) {
            CP_WAIT(1);
        } else {
            CP_WAIT(0);
        }
        __syncthreads();

        const uint32_t st = sb + (c % 3) * STG;
        #pragma unroll
        for (int ks = 0; ks < 4; ks++) {
            const uint32_t kb = ks * 32 + lsel * 16;
            uint32_t ah[4][4], al[4][4], bh[8][2];
            #pragma unroll
            for (int mt = 0; mt < 4; mt++) {
                const uint32_t ro = (uint32_t)(wm * 64 + mt * 16 + lrow) * 128 + kb;
                ldsm4(ah[mt], st + OA_HI + SW128(ro));
                ldsm4(al[mt], st + OA_LO + SW128(ro));
            }
            #pragma unroll
            for (int g = 0; g < 4; g++) {
                const uint32_t ro = (uint32_t)(wn * 64 + g * 16 + lrow) * 128 + kb;
                uint32_t t[4];
                ldsm4(t, st + OB_HI + SW128(ro));
                bh[2 * g][0] = t[0]; bh[2 * g + 1][0] = t[1];
                bh[2 * g][1] = t[2]; bh[2 * g + 1][1] = t[3];
            }
            // Pass-major MMA order: no same-acc RAW within a pass.
            #pragma unroll
            for (int mt = 0; mt < 4; mt++)
                #pragma unroll
                for (int nt = 0; nt < 8; nt++)
                    hmma(acc[mt][nt], ah[mt], bh[nt]);   // hi*hi
            #pragma unroll
            for (int mt = 0; mt < 4; mt++)
                #pragma unroll
                for (int nt = 0; nt < 8; nt++)
                    hmma(acc[mt][nt], al[mt], bh[nt]);   // lo*hi
        }
        __syncthreads();
    }

    // ---- epilogue: bias + exact GELU ----
    #pragma unroll
    for (int mt = 0; mt < 4; mt++) {
        const int mA = m0 + wm * 64 + mt * 16 + (lane >> 2);
        #pragma unroll
        for (int nt = 0; nt < 8; nt++) {
            const int nloc = wn * 64 + nt * 8 + (lane & 3) * 2;
            const int n = n0 + nloc;
            const float b0 = sbias[nloc], b1 = sbias[nloc + 1];
            float v00 = gelu_exact(acc[mt][nt][0] + b0);
            float v01 = gelu_exact(acc[mt][nt][1] + b1);
            float v10 = gelu_exact(acc[mt][nt][2] + b0);
            float v11 = gelu_exact(acc[mt][nt][3] + b1);
            if (MODE == 0) {
                __half h0, h1, l0, l1;
                splitH(v00, h0, l0); splitH(v01, h1, l1);
                *(__half2*)&Zhi[(size_t)mA * H_DIM + n] = __halves2half2(h0, h1);
                *(__half2*)&Zlo[(size_t)mA * H_DIM + n] = __halves2half2(l0, l1);
                splitH(v10, h0, l0); splitH(v11, h1, l1);
                *(__half2*)&Zhi[(size_t)(mA + 8) * H_DIM + n] = __halves2half2(h0, h1);
                *(__half2*)&Zlo[(size_t)(mA + 8) * H_DIM + n] = __halves2half2(l0, l1);
            } else {
                *(float2*)&Out[(size_t)mA * H_DIM + n]       = make_float2(v00, v01);
                *(float2*)&Out[(size_t)(mA + 8) * H_DIM + n] = make_float2(v10, v11);
            }
        }
    }
}

// ---------------- launch ----------------
extern "C" void kernel_launch(void* const* d_in, const int* in_sizes, int n_in,
                              void* d_out, int out_size) {
    const float* emb   = (const float*)d_in[0];
    const void*  spans = d_in[1];
    const float* W1    = (const float*)d_in[2];
    const float* b1    = (const float*)d_in[3];
    const float* W2    = (const float*)d_in[4];
    const float* b2    = (const float*)d_in[5];
    float*       out   = (float*)d_out;

    __half *fh, *fl, *zh, *zl, *w1h, *w2h;
    cudaGetSymbolAddress((void**)&fh,  g_feat_hi);
    cudaGetSymbolAddress((void**)&fl,  g_feat_lo);
    cudaGetSymbolAddress((void**)&zh,  g_z_hi);
    cudaGetSymbolAddress((void**)&zl,  g_z_lo);
    cudaGetSymbolAddress((void**)&w1h, g_w1t_hi);
    cudaGetSymbolAddress((void**)&w2h, g_w2t_hi);

    cudaFuncSetAttribute(gemm_hmma<0>, cudaFuncAttributeMaxDynamicSharedMemorySize, SMEM_TOTAL);
    cudaFuncSetAttribute(gemm_hmma<1>, cudaFuncAttributeMaxDynamicSharedMemorySize, SMEM_TOTAL);

    // weight transpose + fp16 round (hi only)
    wsplit_kernel<<<dim3(H_DIM / 32, K1 / 32), 256>>>(W1, w1h, K1, H_DIM);
    wsplit_kernel<<<dim3(H_DIM / 32, H_DIM / 32), 256>>>(W2, w2h, H_DIM, H_DIM);

    detect_spans_dtype<<<1, 32>>>(spans);
    gather_kernel<<<S_SPANS, 192>>>(emb, spans);

    // z = gelu(feat @ W1^T + b1): M=16384, N=768, K=2304
    gemm_hmma<0><<<dim3(H_DIM / BN, S_SPANS / BM), 256, SMEM_TOTAL>>>(
        fh, fl, w1h, b1, zh, zl, nullptr, K1);
    // out = gelu(z @ W2^T + b2): M=16384, N=768, K=768
    gemm_hmma<1><<<dim3(H_DIM / BN, S_SPANS / BM), 256, SMEM_TOTAL>>>(
        zh, zl, w2h, b2, nullptr, nullptr, out, H_DIM);
}